// round 1
// baseline (speedup 1.0000x reference)
#include <cuda_runtime.h>
#include <math.h>

// Problem constants
#define B_ 2
#define S_ 2048
#define D_ 1024
#define H_ 16
#define DEPTH_ 64
#define M_ (B_ * S_)            // 4096 rows for projections
#define BH_ (B_ * H_)           // 32 batched heads
#define OUT_ELEMS (B_ * S_ * D_)                 // 4,194,304
#define ATTN_ELEMS ((size_t)B_ * H_ * S_ * S_)   // 134,217,728

// Scratch (allocation-free rule: __device__ globals)
__device__ float g_Qh[(size_t)BH_ * S_ * DEPTH_];   // [BH, S, 64]
__device__ float g_Kh[(size_t)BH_ * S_ * DEPTH_];
__device__ float g_Vh[(size_t)BH_ * S_ * DEPTH_];
__device__ float g_ctx[(size_t)M_ * D_];            // [B*S, 1024] (heads merged)
__device__ float g_attn_scratch[ATTN_ELEMS];        // used only if d_out lacks attn

// ---------------------------------------------------------------------------
// Projection GEMM: P = X @ W + b.   X:[M,K] W:[K,N] b:[N]
// 128x128 tile, K-chunks of 8, 256 threads, 8x8 per-thread microtile.
// headsplit=1: write to [B,H,S,64]; headsplit=0: row-major [M,N].
// ---------------------------------------------------------------------------
__global__ __launch_bounds__(256) void proj_kernel(
    const float* __restrict__ X, const float* __restrict__ W,
    const float* __restrict__ bias, float* __restrict__ out,
    int M, int K, int N, int headsplit)
{
    __shared__ float As[8][128];
    __shared__ float Bs[8][128];
    const int tid = threadIdx.x;
    const int tx = tid & 15;          // 0..15 col group
    const int ty = tid >> 4;          // 0..15 row group
    const int row0 = blockIdx.y * 128;
    const int col0 = blockIdx.x * 128;

    float acc[8][8];
#pragma unroll
    for (int i = 0; i < 8; i++)
#pragma unroll
        for (int j = 0; j < 8; j++) acc[i][j] = 0.f;

    for (int k0 = 0; k0 < K; k0 += 8) {
        // A tile: 128 rows x 8 k
#pragma unroll
        for (int i = tid; i < 128 * 8; i += 256) {
            int r = i >> 3, c = i & 7;
            As[c][r] = X[(size_t)(row0 + r) * K + k0 + c];
        }
        // B tile: 8 k x 128 cols
#pragma unroll
        for (int i = tid; i < 8 * 128; i += 256) {
            int r = i >> 7, c = i & 127;
            Bs[r][c] = W[(size_t)(k0 + r) * N + col0 + c];
        }
        __syncthreads();
#pragma unroll
        for (int kk = 0; kk < 8; kk++) {
            float a[8], b[8];
#pragma unroll
            for (int i = 0; i < 8; i++) a[i] = As[kk][ty * 8 + i];
#pragma unroll
            for (int j = 0; j < 8; j++) b[j] = Bs[kk][tx * 8 + j];
#pragma unroll
            for (int i = 0; i < 8; i++)
#pragma unroll
                for (int j = 0; j < 8; j++) acc[i][j] += a[i] * b[j];
        }
        __syncthreads();
    }

#pragma unroll
    for (int i = 0; i < 8; i++) {
        int row = row0 + ty * 8 + i;
#pragma unroll
        for (int j = 0; j < 8; j++) {
            int col = col0 + tx * 8 + j;
            float v = acc[i][j] + bias[col];
            if (headsplit) {
                int b = row >> 11, s = row & 2047;
                int h = col >> 6, d = col & 63;
                out[((size_t)(b * H_ + h) * S_ + s) * DEPTH_ + d] = v;
            } else {
                out[(size_t)row * N + col] = v;
            }
        }
    }
}

// ---------------------------------------------------------------------------
// Logits: for each bh: C = Qh[S,64] @ Kh[S,64]^T * 0.125 + mask*1e-9
// 128x128 tile, K=64 in chunks of 8. grid (ktile=16, qtile=16, bh=32)
// ---------------------------------------------------------------------------
__global__ __launch_bounds__(256) void logits_kernel(
    const float* __restrict__ Qh, const float* __restrict__ Kh,
    const float* __restrict__ mask, float* __restrict__ attn)
{
    const int bh = blockIdx.z;
    const float* A = Qh + (size_t)bh * S_ * DEPTH_;
    const float* Bm = Kh + (size_t)bh * S_ * DEPTH_;
    float* C = attn + (size_t)bh * S_ * S_;
    const int bidx = bh >> 4;  // batch index for mask

    __shared__ float As[8][128];
    __shared__ float Bs[8][128];
    const int tid = threadIdx.x;
    const int tx = tid & 15;
    const int ty = tid >> 4;
    const int row0 = blockIdx.y * 128;   // q rows
    const int col0 = blockIdx.x * 128;   // k cols

    float acc[8][8];
#pragma unroll
    for (int i = 0; i < 8; i++)
#pragma unroll
        for (int j = 0; j < 8; j++) acc[i][j] = 0.f;

    for (int k0 = 0; k0 < DEPTH_; k0 += 8) {
#pragma unroll
        for (int i = tid; i < 128 * 8; i += 256) {
            int r = i >> 3, c = i & 7;
            As[c][r] = A[(size_t)(row0 + r) * DEPTH_ + k0 + c];
        }
        // B^T tile: Bs[d][kcol] = Kh[col0+kcol][k0+d]
#pragma unroll
        for (int i = tid; i < 128 * 8; i += 256) {
            int r = i >> 3, c = i & 7;   // r = kcol-local, c = d-local
            Bs[c][r] = Bm[(size_t)(col0 + r) * DEPTH_ + k0 + c];
        }
        __syncthreads();
#pragma unroll
        for (int kk = 0; kk < 8; kk++) {
            float a[8], b[8];
#pragma unroll
            for (int i = 0; i < 8; i++) a[i] = As[kk][ty * 8 + i];
#pragma unroll
            for (int j = 0; j < 8; j++) b[j] = Bs[kk][tx * 8 + j];
#pragma unroll
            for (int i = 0; i < 8; i++)
#pragma unroll
                for (int j = 0; j < 8; j++) acc[i][j] += a[i] * b[j];
        }
        __syncthreads();
    }

#pragma unroll
    for (int i = 0; i < 8; i++) {
        int q = row0 + ty * 8 + i;
#pragma unroll
        for (int j = 0; j < 8; j++) {
            int kc = col0 + tx * 8 + j;
            float v = acc[i][j] * 0.125f
                      + mask[((size_t)bidx * S_ + q) * S_ + kc] * 1e-9f;
            C[(size_t)q * S_ + kc] = v;
        }
    }
}

// ---------------------------------------------------------------------------
// Row softmax over 2048 elements, in place. One block per row, 256 threads.
// ---------------------------------------------------------------------------
__global__ __launch_bounds__(256) void softmax_kernel(float* __restrict__ attn)
{
    float* p = attn + (size_t)blockIdx.x * S_;
    const int tid = threadIdx.x;
    __shared__ float red[256];

    float v[8];
    float m = -INFINITY;
#pragma unroll
    for (int i = 0; i < 8; i++) {
        v[i] = p[tid + i * 256];
        m = fmaxf(m, v[i]);
    }
    red[tid] = m;
    __syncthreads();
    for (int s = 128; s > 0; s >>= 1) {
        if (tid < s) red[tid] = fmaxf(red[tid], red[tid + s]);
        __syncthreads();
    }
    m = red[0];
    __syncthreads();

    float sum = 0.f;
#pragma unroll
    for (int i = 0; i < 8; i++) {
        v[i] = expf(v[i] - m);
        sum += v[i];
    }
    red[tid] = sum;
    __syncthreads();
    for (int s = 128; s > 0; s >>= 1) {
        if (tid < s) red[tid] += red[tid + s];
        __syncthreads();
    }
    float inv = 1.f / red[0];
#pragma unroll
    for (int i = 0; i < 8; i++) p[tid + i * 256] = v[i] * inv;
}

// ---------------------------------------------------------------------------
// ctx = attn[S,S] @ Vh[S,64] per bh; write merged-head layout [B*S, 1024].
// Block: 128 q-rows x 64 cols, K-chunks of 16. grid (qtile=16, bh=32).
// 256 threads, each 8x4 microtile.
// ---------------------------------------------------------------------------
__global__ __launch_bounds__(256) void ctx_kernel(
    const float* __restrict__ attn, const float* __restrict__ Vh,
    float* __restrict__ ctx)
{
    const int bh = blockIdx.y;
    const float* A = attn + (size_t)bh * S_ * S_;
    const float* Bm = Vh + (size_t)bh * S_ * DEPTH_;
    const int b = bh >> 4, h = bh & 15;

    __shared__ float As[16][128];
    __shared__ float Bs[16][64];
    const int tid = threadIdx.x;
    const int tx = tid & 15;          // col group (4 cols)
    const int ty = tid >> 4;          // row group (8 rows)
    const int row0 = blockIdx.x * 128;

    float acc[8][4];
#pragma unroll
    for (int i = 0; i < 8; i++)
#pragma unroll
        for (int j = 0; j < 4; j++) acc[i][j] = 0.f;

    for (int k0 = 0; k0 < S_; k0 += 16) {
#pragma unroll
        for (int i = tid; i < 128 * 16; i += 256) {
            int r = i >> 4, c = i & 15;
            As[c][r] = A[(size_t)(row0 + r) * S_ + k0 + c];
        }
#pragma unroll
        for (int i = tid; i < 16 * 64; i += 256) {
            int r = i >> 6, c = i & 63;
            Bs[r][c] = Bm[(size_t)(k0 + r) * DEPTH_ + c];
        }
        __syncthreads();
#pragma unroll
        for (int kk = 0; kk < 16; kk++) {
            float a[8], bb[4];
#pragma unroll
            for (int i = 0; i < 8; i++) a[i] = As[kk][ty * 8 + i];
#pragma unroll
            for (int j = 0; j < 4; j++) bb[j] = Bs[kk][tx * 4 + j];
#pragma unroll
            for (int i = 0; i < 8; i++)
#pragma unroll
                for (int j = 0; j < 4; j++) acc[i][j] += a[i] * bb[j];
        }
        __syncthreads();
    }

#pragma unroll
    for (int i = 0; i < 8; i++) {
        int s = row0 + ty * 8 + i;
#pragma unroll
        for (int j = 0; j < 4; j++) {
            int d = tx * 4 + j;
            ctx[((size_t)(b * S_ + s)) * D_ + h * DEPTH_ + d] = acc[i][j];
        }
    }
}

// ---------------------------------------------------------------------------
extern "C" void kernel_launch(void* const* d_in, const int* in_sizes, int n_in,
                              void* d_out, int out_size)
{
    const float* q    = (const float*)d_in[0];
    const float* k    = (const float*)d_in[1];
    const float* v    = (const float*)d_in[2];
    const float* mask = (const float*)d_in[3];
    const float* wq   = (const float*)d_in[4];
    const float* bq   = (const float*)d_in[5];
    const float* wk   = (const float*)d_in[6];
    const float* bk   = (const float*)d_in[7];
    const float* wv   = (const float*)d_in[8];
    const float* bv   = (const float*)d_in[9];
    const float* wo   = (const float*)d_in[10];
    const float* bo   = (const float*)d_in[11];

    float* out = (float*)d_out;

    // attn output location: concatenated after out if the harness buffer holds it
    float* attn;
    if ((size_t)out_size >= (size_t)OUT_ELEMS + ATTN_ELEMS) {
        attn = out + OUT_ELEMS;
    } else {
        cudaGetSymbolAddress((void**)&attn, g_attn_scratch);
    }

    float *Qh, *Kh, *Vh, *ctx;
    cudaGetSymbolAddress((void**)&Qh, g_Qh);
    cudaGetSymbolAddress((void**)&Kh, g_Kh);
    cudaGetSymbolAddress((void**)&Vh, g_Vh);
    cudaGetSymbolAddress((void**)&ctx, g_ctx);

    dim3 projGrid(D_ / 128, M_ / 128);            // (8, 32)
    proj_kernel<<<projGrid, 256>>>(q, wq, bq, Qh, M_, D_, D_, 1);
    proj_kernel<<<projGrid, 256>>>(k, wk, bk, Kh, M_, D_, D_, 1);
    proj_kernel<<<projGrid, 256>>>(v, wv, bv, Vh, M_, D_, D_, 1);

    dim3 logitsGrid(S_ / 128, S_ / 128, BH_);     // (16, 16, 32)
    logits_kernel<<<logitsGrid, 256>>>(Qh, Kh, mask, attn);

    softmax_kernel<<<BH_ * S_, 256>>>(attn);      // 65536 rows

    dim3 ctxGrid(S_ / 128, BH_);                  // (16, 32)
    ctx_kernel<<<ctxGrid, 256>>>(attn, Vh, ctx);

    proj_kernel<<<projGrid, 256>>>(ctx, wo, bo, out, M_, D_, D_, 0);
}

// round 2
// speedup vs baseline: 1.6253x; 1.6253x over previous
#include <cuda_runtime.h>
#include <math.h>

// Problem constants
#define B_ 2
#define S_ 2048
#define D_ 1024
#define H_ 16
#define DEPTH_ 64
#define M_ (B_ * S_)            // 4096 rows for projections
#define BH_ (B_ * H_)           // 32 batched heads
#define OUT_ELEMS (B_ * S_ * D_)                 // 4,194,304
#define ATTN_ELEMS ((size_t)B_ * H_ * S_ * S_)   // 134,217,728

// Scratch (allocation-free rule: __device__ globals)
__device__ float g_Qh[(size_t)BH_ * S_ * DEPTH_];   // [BH, S, 64]
__device__ float g_Kh[(size_t)BH_ * S_ * DEPTH_];
__device__ float g_Vh[(size_t)BH_ * S_ * DEPTH_];
__device__ float g_ctx[(size_t)M_ * D_];            // [B*S, 1024] (heads merged)
__device__ float g_attn_scratch[ATTN_ELEMS];        // used only if d_out lacks attn

// ---------------------------------------------------------------------------
// Projection GEMM: P = X @ W + b.   X:[M,K] W:[K,N] b:[N]
// 128x128 tile, K-chunks of 16, 256 threads, 8x8 microtile, float4 LDS.
// headsplit=1: write to [B,H,S,64]; headsplit=0: row-major [M,N].
// ---------------------------------------------------------------------------
__global__ __launch_bounds__(256) void proj_kernel(
    const float* __restrict__ X, const float* __restrict__ W,
    const float* __restrict__ bias, float* __restrict__ out,
    int M, int K, int N, int headsplit)
{
    __shared__ float As[16][128];   // K-major
    __shared__ float Bs[16][128];
    const int tid = threadIdx.x;
    const int tx = tid & 15;          // col group
    const int ty = tid >> 4;          // row group
    const int row0 = blockIdx.y * 128;
    const int col0 = blockIdx.x * 128;

    float acc[8][8];
#pragma unroll
    for (int i = 0; i < 8; i++)
#pragma unroll
        for (int j = 0; j < 8; j++) acc[i][j] = 0.f;

    for (int k0 = 0; k0 < K; k0 += 16) {
        // A tile: 128 rows x 16 k  (512 float4 loads, scatter-transpose)
#pragma unroll
        for (int i = tid; i < 512; i += 256) {
            int r = i >> 2, c4 = i & 3;
            float4 x = *(const float4*)(X + (size_t)(row0 + r) * K + k0 + c4 * 4);
            As[c4 * 4 + 0][r] = x.x;
            As[c4 * 4 + 1][r] = x.y;
            As[c4 * 4 + 2][r] = x.z;
            As[c4 * 4 + 3][r] = x.w;
        }
        // B tile: 16 k x 128 cols (512 float4 loads, direct)
#pragma unroll
        for (int i = tid; i < 512; i += 256) {
            int r = i >> 5, c4 = i & 31;
            *(float4*)&Bs[r][c4 * 4] =
                *(const float4*)(W + (size_t)(k0 + r) * N + col0 + c4 * 4);
        }
        __syncthreads();
#pragma unroll
        for (int kk = 0; kk < 16; kk++) {
            float4 a0 = *(const float4*)&As[kk][ty * 8];
            float4 a1 = *(const float4*)&As[kk][ty * 8 + 4];
            float4 b0 = *(const float4*)&Bs[kk][tx * 8];
            float4 b1 = *(const float4*)&Bs[kk][tx * 8 + 4];
            float a[8] = {a0.x, a0.y, a0.z, a0.w, a1.x, a1.y, a1.z, a1.w};
            float b[8] = {b0.x, b0.y, b0.z, b0.w, b1.x, b1.y, b1.z, b1.w};
#pragma unroll
            for (int i = 0; i < 8; i++)
#pragma unroll
                for (int j = 0; j < 8; j++) acc[i][j] += a[i] * b[j];
        }
        __syncthreads();
    }

    float4 bias0 = *(const float4*)(bias + col0 + tx * 8);
    float4 bias1 = *(const float4*)(bias + col0 + tx * 8 + 4);
#pragma unroll
    for (int i = 0; i < 8; i++) {
        int row = row0 + ty * 8 + i;
        float4 v0 = make_float4(acc[i][0] + bias0.x, acc[i][1] + bias0.y,
                                acc[i][2] + bias0.z, acc[i][3] + bias0.w);
        float4 v1 = make_float4(acc[i][4] + bias1.x, acc[i][5] + bias1.y,
                                acc[i][6] + bias1.z, acc[i][7] + bias1.w);
        int col = col0 + tx * 8;
        if (headsplit) {
            int b = row >> 11, s = row & 2047;
            int h = col >> 6, d = col & 63;
            float* dst = out + ((size_t)(b * H_ + h) * S_ + s) * DEPTH_ + d;
            *(float4*)dst = v0;
            *(float4*)(dst + 4) = v1;
        } else {
            float* dst = out + (size_t)row * N + col;
            *(float4*)dst = v0;
            *(float4*)(dst + 4) = v1;
        }
    }
}

// ---------------------------------------------------------------------------
// Logits: per bh: C = Qh[S,64] @ Kh[S,64]^T * 0.125 + mask*1e-9
// 128x128 tile, K=64 in chunks of 16. grid (16, 16, 32)
// ---------------------------------------------------------------------------
__global__ __launch_bounds__(256) void logits_kernel(
    const float* __restrict__ Qh, const float* __restrict__ Kh,
    const float* __restrict__ mask, float* __restrict__ attn)
{
    const int bh = blockIdx.z;
    const float* A = Qh + (size_t)bh * S_ * DEPTH_;
    const float* Bm = Kh + (size_t)bh * S_ * DEPTH_;
    float* C = attn + (size_t)bh * S_ * S_;
    const int bidx = bh >> 4;  // batch index for mask

    __shared__ float As[16][128];
    __shared__ float Bs[16][128];
    const int tid = threadIdx.x;
    const int tx = tid & 15;
    const int ty = tid >> 4;
    const int row0 = blockIdx.y * 128;   // q rows
    const int col0 = blockIdx.x * 128;   // k cols

    float acc[8][8];
#pragma unroll
    for (int i = 0; i < 8; i++)
#pragma unroll
        for (int j = 0; j < 8; j++) acc[i][j] = 0.f;

#pragma unroll
    for (int k0 = 0; k0 < DEPTH_; k0 += 16) {
        // Q tile: scatter-transpose
#pragma unroll
        for (int i = tid; i < 512; i += 256) {
            int r = i >> 2, c4 = i & 3;
            float4 x = *(const float4*)(A + (size_t)(row0 + r) * DEPTH_ + k0 + c4 * 4);
            As[c4 * 4 + 0][r] = x.x;
            As[c4 * 4 + 1][r] = x.y;
            As[c4 * 4 + 2][r] = x.z;
            As[c4 * 4 + 3][r] = x.w;
        }
        // K^T tile: Bs[d][kcol] — scatter-transpose from K rows
#pragma unroll
        for (int i = tid; i < 512; i += 256) {
            int r = i >> 2, c4 = i & 3;   // r = kcol-local
            float4 x = *(const float4*)(Bm + (size_t)(col0 + r) * DEPTH_ + k0 + c4 * 4);
            Bs[c4 * 4 + 0][r] = x.x;
            Bs[c4 * 4 + 1][r] = x.y;
            Bs[c4 * 4 + 2][r] = x.z;
            Bs[c4 * 4 + 3][r] = x.w;
        }
        __syncthreads();
#pragma unroll
        for (int kk = 0; kk < 16; kk++) {
            float4 a0 = *(const float4*)&As[kk][ty * 8];
            float4 a1 = *(const float4*)&As[kk][ty * 8 + 4];
            float4 b0 = *(const float4*)&Bs[kk][tx * 8];
            float4 b1 = *(const float4*)&Bs[kk][tx * 8 + 4];
            float a[8] = {a0.x, a0.y, a0.z, a0.w, a1.x, a1.y, a1.z, a1.w};
            float b[8] = {b0.x, b0.y, b0.z, b0.w, b1.x, b1.y, b1.z, b1.w};
#pragma unroll
            for (int i = 0; i < 8; i++)
#pragma unroll
                for (int j = 0; j < 8; j++) acc[i][j] += a[i] * b[j];
        }
        __syncthreads();
    }

#pragma unroll
    for (int i = 0; i < 8; i++) {
        int q = row0 + ty * 8 + i;
        int kc = col0 + tx * 8;
        const float* mrow = mask + ((size_t)bidx * S_ + q) * S_ + kc;
        float4 m0 = *(const float4*)mrow;
        float4 m1 = *(const float4*)(mrow + 4);
        float4 v0 = make_float4(acc[i][0] * 0.125f + m0.x * 1e-9f,
                                acc[i][1] * 0.125f + m0.y * 1e-9f,
                                acc[i][2] * 0.125f + m0.z * 1e-9f,
                                acc[i][3] * 0.125f + m0.w * 1e-9f);
        float4 v1 = make_float4(acc[i][4] * 0.125f + m1.x * 1e-9f,
                                acc[i][5] * 0.125f + m1.y * 1e-9f,
                                acc[i][6] * 0.125f + m1.z * 1e-9f,
                                acc[i][7] * 0.125f + m1.w * 1e-9f);
        float* dst = C + (size_t)q * S_ + kc;
        *(float4*)dst = v0;
        *(float4*)(dst + 4) = v1;
    }
}

// ---------------------------------------------------------------------------
// Row softmax over 2048 elements, in place. One block per row, 256 threads.
// ---------------------------------------------------------------------------
__global__ __launch_bounds__(256) void softmax_kernel(float* __restrict__ attn)
{
    float4* p = (float4*)(attn + (size_t)blockIdx.x * S_);
    const int tid = threadIdx.x;
    const int lane = tid & 31, warp = tid >> 5;
    __shared__ float red[8];

    float4 v0 = p[tid];
    float4 v1 = p[tid + 256];

    float m = fmaxf(fmaxf(fmaxf(v0.x, v0.y), fmaxf(v0.z, v0.w)),
                    fmaxf(fmaxf(v1.x, v1.y), fmaxf(v1.z, v1.w)));
#pragma unroll
    for (int s = 16; s > 0; s >>= 1) m = fmaxf(m, __shfl_xor_sync(~0u, m, s));
    if (lane == 0) red[warp] = m;
    __syncthreads();
    m = red[lane & 7];
#pragma unroll
    for (int s = 4; s > 0; s >>= 1) m = fmaxf(m, __shfl_xor_sync(~0u, m, s));

    v0.x = __expf(v0.x - m); v0.y = __expf(v0.y - m);
    v0.z = __expf(v0.z - m); v0.w = __expf(v0.w - m);
    v1.x = __expf(v1.x - m); v1.y = __expf(v1.y - m);
    v1.z = __expf(v1.z - m); v1.w = __expf(v1.w - m);

    float sum = (v0.x + v0.y) + (v0.z + v0.w) + (v1.x + v1.y) + (v1.z + v1.w);
#pragma unroll
    for (int s = 16; s > 0; s >>= 1) sum += __shfl_xor_sync(~0u, sum, s);
    __syncthreads();
    if (lane == 0) red[warp] = sum;
    __syncthreads();
    sum = red[lane & 7];
#pragma unroll
    for (int s = 4; s > 0; s >>= 1) sum += __shfl_xor_sync(~0u, sum, s);

    float inv = 1.f / sum;
    v0.x *= inv; v0.y *= inv; v0.z *= inv; v0.w *= inv;
    v1.x *= inv; v1.y *= inv; v1.z *= inv; v1.w *= inv;
    p[tid] = v0;
    p[tid + 256] = v1;
}

// ---------------------------------------------------------------------------
// ctx = attn[S,S] @ Vh[S,64] per bh; write merged-head layout [B*S, 1024].
// Tile: 256 q-rows x 64 cols, K-chunks of 16, 8x8 microtile. grid (8, 32).
// ---------------------------------------------------------------------------
__global__ __launch_bounds__(256) void ctx_kernel(
    const float* __restrict__ attn, const float* __restrict__ Vh,
    float* __restrict__ ctx)
{
    const int bh = blockIdx.y;
    const float* A = attn + (size_t)bh * S_ * S_;
    const float* Bm = Vh + (size_t)bh * S_ * DEPTH_;
    const int b = bh >> 4, h = bh & 15;

    __shared__ float As[16][256];
    __shared__ float Bs[16][64];
    const int tid = threadIdx.x;
    const int tx = tid & 7;           // col group (8 cols)
    const int ty = tid >> 3;          // row group (8 rows, 32 groups -> 256 rows)
    const int row0 = blockIdx.x * 256;

    float acc[8][8];
#pragma unroll
    for (int i = 0; i < 8; i++)
#pragma unroll
        for (int j = 0; j < 8; j++) acc[i][j] = 0.f;

    for (int k0 = 0; k0 < S_; k0 += 16) {
        // attn tile: 256 rows x 16 k, scatter-transpose (1024 float4 loads)
#pragma unroll
        for (int i = tid; i < 1024; i += 256) {
            int r = i >> 2, c4 = i & 3;
            float4 x = *(const float4*)(A + (size_t)(row0 + r) * S_ + k0 + c4 * 4);
            As[c4 * 4 + 0][r] = x.x;
            As[c4 * 4 + 1][r] = x.y;
            As[c4 * 4 + 2][r] = x.z;
            As[c4 * 4 + 3][r] = x.w;
        }
        // V tile: 16 k x 64 cols (256 float4 loads, direct)
        {
            int r = tid >> 4, c4 = tid & 15;
            *(float4*)&Bs[r][c4 * 4] =
                *(const float4*)(Bm + (size_t)(k0 + r) * DEPTH_ + c4 * 4);
        }
        __syncthreads();
#pragma unroll
        for (int kk = 0; kk < 16; kk++) {
            float4 a0 = *(const float4*)&As[kk][ty * 8];
            float4 a1 = *(const float4*)&As[kk][ty * 8 + 4];
            float4 b0 = *(const float4*)&Bs[kk][tx * 8];
            float4 b1 = *(const float4*)&Bs[kk][tx * 8 + 4];
            float a[8] = {a0.x, a0.y, a0.z, a0.w, a1.x, a1.y, a1.z, a1.w};
            float bb[8] = {b0.x, b0.y, b0.z, b0.w, b1.x, b1.y, b1.z, b1.w};
#pragma unroll
            for (int i = 0; i < 8; i++)
#pragma unroll
                for (int j = 0; j < 8; j++) acc[i][j] += a[i] * bb[j];
        }
        __syncthreads();
    }

#pragma unroll
    for (int i = 0; i < 8; i++) {
        int s = row0 + ty * 8 + i;
        float* dst = ctx + ((size_t)(b * S_ + s)) * D_ + h * DEPTH_ + tx * 8;
        *(float4*)dst = make_float4(acc[i][0], acc[i][1], acc[i][2], acc[i][3]);
        *(float4*)(dst + 4) = make_float4(acc[i][4], acc[i][5], acc[i][6], acc[i][7]);
    }
}

// ---------------------------------------------------------------------------
extern "C" void kernel_launch(void* const* d_in, const int* in_sizes, int n_in,
                              void* d_out, int out_size)
{
    const float* q    = (const float*)d_in[0];
    const float* k    = (const float*)d_in[1];
    const float* v    = (const float*)d_in[2];
    const float* mask = (const float*)d_in[3];
    const float* wq   = (const float*)d_in[4];
    const float* bq   = (const float*)d_in[5];
    const float* wk   = (const float*)d_in[6];
    const float* bk   = (const float*)d_in[7];
    const float* wv   = (const float*)d_in[8];
    const float* bv   = (const float*)d_in[9];
    const float* wo   = (const float*)d_in[10];
    const float* bo   = (const float*)d_in[11];

    float* out = (float*)d_out;

    // attn output location: concatenated after out if the harness buffer holds it
    float* attn;
    if ((size_t)out_size >= (size_t)OUT_ELEMS + ATTN_ELEMS) {
        attn = out + OUT_ELEMS;
    } else {
        cudaGetSymbolAddress((void**)&attn, g_attn_scratch);
    }

    float *Qh, *Kh, *Vh, *ctx;
    cudaGetSymbolAddress((void**)&Qh, g_Qh);
    cudaGetSymbolAddress((void**)&Kh, g_Kh);
    cudaGetSymbolAddress((void**)&Vh, g_Vh);
    cudaGetSymbolAddress((void**)&ctx, g_ctx);

    dim3 projGrid(D_ / 128, M_ / 128);            // (8, 32)
    proj_kernel<<<projGrid, 256>>>(q, wq, bq, Qh, M_, D_, D_, 1);
    proj_kernel<<<projGrid, 256>>>(k, wk, bk, Kh, M_, D_, D_, 1);
    proj_kernel<<<projGrid, 256>>>(v, wv, bv, Vh, M_, D_, D_, 1);

    dim3 logitsGrid(S_ / 128, S_ / 128, BH_);     // (16, 16, 32)
    logits_kernel<<<logitsGrid, 256>>>(Qh, Kh, mask, attn);

    softmax_kernel<<<BH_ * S_, 256>>>(attn);      // 65536 rows

    dim3 ctxGrid(S_ / 256, BH_);                  // (8, 32)
    ctx_kernel<<<ctxGrid, 256>>>(attn, Vh, ctx);

    proj_kernel<<<projGrid, 256>>>(ctx, wo, bo, out, M_, D_, D_, 0);
}